// round 15
// baseline (speedup 1.0000x reference)
#include <cuda_runtime.h>
#include <cstdint>

// Problem constants
#define T_STEPS   32768
#define RDIM      1024
#define IN_DIM    128
#define OUT_DIM   64

// Scan config: 64 persistent blocks x 256 threads.
// Per block: 16 rows of W. Per thread: 8 rows x 8 cols (64 fp32 weights in regs).
#define GBLK      64
#define TPB       256
#define RPB       16

// ---------------- static device scratch (no allocations allowed) -------------
__device__ float g_u[(size_t)T_STEPS * RDIM];          // 128 MB  u[t][r]
// State stored as (value, tag) pairs: g_sp[t][r] = {bits(s_{t-1}[r]), tag}
// Row t is valid when tag == t. Row 0 = zeros with tag 0.
// All pair accesses during the scan are 64-bit relaxed atomics => no tearing.
__device__ uint2 g_sp[(size_t)(T_STEPS + 1) * RDIM];   // 268 MB

// ---------------- clear tags each launch (graph replays reuse buffers) ------
__global__ void k_clear() {
    const size_t n = (size_t)(T_STEPS + 1) * RDIM / 2;   // uint4 count (2 pairs each)
    uint4* p = (uint4*)g_sp;
    for (size_t i = (size_t)blockIdx.x * blockDim.x + threadIdx.x; i < n;
         i += (size_t)gridDim.x * blockDim.x) {
        unsigned row = (unsigned)(i >> 9);               // (i*2)/1024
        unsigned tag = (row == 0) ? 0u : 0xFFFFFFFFu;    // row0 valid (tag 0, val 0)
        p[i] = make_uint4(0u, tag, 0u, tag);
    }
}

// ---------------- accurate tanh (err ~1e-7, no overflow) --------------------
__device__ __forceinline__ float tanh_acc(float x) {
    float ax = fabsf(x);
    float z = exp2f(-2.8853900817779268f * ax);   // e^{-2|x|}
    float t = __fdividef(1.0f - z, 1.0f + z);
    return copysignf(t, x);
}

// ---------------- 64-bit relaxed atomic pair access -------------------------
__device__ __forceinline__ void pair_ld(const uint2* p, unsigned& lo, unsigned& hi) {
    asm volatile("{\n\t.reg .b64 d;\n\t"
                 "ld.relaxed.gpu.b64 d, [%2];\n\t"
                 "mov.b64 {%0,%1}, d;\n\t}"
                 : "=r"(lo), "=r"(hi) : "l"(p) : "memory");
}
__device__ __forceinline__ void pair_st(uint2* p, unsigned lo, unsigned hi) {
    asm volatile("{\n\t.reg .b64 d;\n\t"
                 "mov.b64 d, {%1,%2};\n\t"
                 "st.relaxed.gpu.b64 [%0], d;\n\t}"
                 :: "l"(p), "r"(lo), "r"(hi) : "memory");
}

// =============================================================================
// Kernel 1: u[t][r] = sum_k input[t][k] * Win[r][k]   (NT GEMM, 64x64 tiles)
// =============================================================================
__global__ __launch_bounds__(256) void k_u(const float* __restrict__ inp,
                                           const float* __restrict__ win) {
    __shared__ float As[64][68];  // As[k][t]
    __shared__ float Bs[64][68];  // Bs[k][r]
    const int t0 = blockIdx.x * 64;
    const int r0 = blockIdx.y * 64;
    const int tid = threadIdx.x;
    const int tx = tid & 15, ty = tid >> 4;

    float acc[4][4];
#pragma unroll
    for (int i = 0; i < 4; i++)
#pragma unroll
        for (int j = 0; j < 4; j++) acc[i][j] = 0.0f;

#pragma unroll
    for (int kc = 0; kc < IN_DIM; kc += 64) {
#pragma unroll
        for (int it = 0; it < 4; it++) {
            int idx = tid + it * 256;          // 0..1023 (float4 slots)
            int tt = idx >> 4;                 // 0..63
            int k4 = idx & 15;                 // 0..15
            float4 va = *(const float4*)(inp + (size_t)(t0 + tt) * IN_DIM + kc + k4 * 4);
            As[k4 * 4 + 0][tt] = va.x; As[k4 * 4 + 1][tt] = va.y;
            As[k4 * 4 + 2][tt] = va.z; As[k4 * 4 + 3][tt] = va.w;
            float4 vb = *(const float4*)(win + (size_t)(r0 + tt) * IN_DIM + kc + k4 * 4);
            Bs[k4 * 4 + 0][tt] = vb.x; Bs[k4 * 4 + 1][tt] = vb.y;
            Bs[k4 * 4 + 2][tt] = vb.z; Bs[k4 * 4 + 3][tt] = vb.w;
        }
        __syncthreads();
#pragma unroll
        for (int k = 0; k < 64; k++) {
            float4 a = *(const float4*)&As[k][ty * 4];
            float4 b = *(const float4*)&Bs[k][tx * 4];
            float av[4] = {a.x, a.y, a.z, a.w};
            float bv[4] = {b.x, b.y, b.z, b.w};
#pragma unroll
            for (int i = 0; i < 4; i++)
#pragma unroll
                for (int j = 0; j < 4; j++) acc[i][j] = fmaf(av[i], bv[j], acc[i][j]);
        }
        __syncthreads();
    }
#pragma unroll
    for (int i = 0; i < 4; i++) {
        float4 o = make_float4(acc[i][0], acc[i][1], acc[i][2], acc[i][3]);
        *(float4*)(g_u + (size_t)(t0 + ty * 4 + i) * RDIM + r0 + tx * 4) = o;
    }
}

// =============================================================================
// Kernel 2: the scan. Flag fused into data: each thread polls the exact
// (value,tag) pairs it consumes via 64-bit relaxed atomics (single-copy
// atomic => a matching tag provably carries its matching value).
// One L2 round trip per step, no hot flag line, no pre-compute barrier.
// =============================================================================
__global__ __launch_bounds__(TPB, 1) void k_scan(const float* __restrict__ W) {
    const int b   = blockIdx.x;
    const int tid = threadIdx.x;
    const int w   = tid >> 5;        // warp 0..7
    const int l   = tid & 31;
    const int g   = w >> 2;          // row group 0..1 (8 rows each)
    const int q   = w & 3;           // col quadrant (256 cols)
    const int rowbase = b * RPB + g * 8;
    const int cbase   = q * 256 + l * 8;

    // 8x8 weight tile in registers for the whole scan
    float4 wv[8][2];
#pragma unroll
    for (int i = 0; i < 8; i++) {
        const float4* p = (const float4*)(W + (size_t)(rowbase + i) * RDIM + cbase);
        wv[i][0] = p[0];
        wv[i][1] = p[1];
    }

    __shared__ float part[2][8][8];  // [parity][warp][row-in-group]

    const bool isOut = (w == 0 && l < 16);
    const int outrow = b * RPB + l;  // valid when isOut
    float s_my = 0.0f;

    for (int t = 0; t < T_STEPS; t++) {
        // prefetch u[t][outrow] (latency hides under poll)
        float uval = 0.0f;
        if (isOut) uval = __ldg(&g_u[(size_t)t * RDIM + outrow]);

        // ---- fused poll+load: my 8 (value,tag) pairs of row t ----
        const uint2* pp = g_sp + (size_t)t * RDIM + cbase;
        const unsigned want = (unsigned)t;
        unsigned val[8];
        for (;;) {
            unsigned tg[8];
#pragma unroll
            for (int j = 0; j < 8; j++) pair_ld(pp + j, val[j], tg[j]);  // MLP=8
            bool ok = (tg[0] == want) & (tg[1] == want) & (tg[2] == want) &
                      (tg[3] == want) & (tg[4] == want) & (tg[5] == want) &
                      (tg[6] == want) & (tg[7] == want);
            if (ok) break;
        }
        const float s0 = __uint_as_float(val[0]), s1 = __uint_as_float(val[1]);
        const float s2 = __uint_as_float(val[2]), s3 = __uint_as_float(val[3]);
        const float s4 = __uint_as_float(val[4]), s5 = __uint_as_float(val[5]);
        const float s6 = __uint_as_float(val[6]), s7 = __uint_as_float(val[7]);

        // 64 FMAs: 8 rows x 8 cols
        float v[8];
#pragma unroll
        for (int i = 0; i < 8; i++) {
            v[i] = wv[i][0].x * s0 + wv[i][0].y * s1 + wv[i][0].z * s2 + wv[i][0].w * s3
                 + wv[i][1].x * s4 + wv[i][1].y * s5 + wv[i][1].z * s6 + wv[i][1].w * s7;
        }

        // exchange-reduction: 23 shfls; lane l<8 ends with total of row rowbase+l
#pragma unroll
        for (int j = 0; j < 8; j++) v[j] += __shfl_xor_sync(0xFFFFFFFFu, v[j], 16);
#pragma unroll
        for (int j = 0; j < 8; j++) v[j] += __shfl_xor_sync(0xFFFFFFFFu, v[j], 8);
        const bool h4 = (l & 4);
        float wr[4];
#pragma unroll
        for (int k = 0; k < 4; k++) {
            float snd = h4 ? v[k] : v[k + 4];
            float got = __shfl_xor_sync(0xFFFFFFFFu, snd, 4);
            wr[k] = (h4 ? v[k + 4] : v[k]) + got;
        }
        const bool h2 = (l & 2);
        float xr[2];
#pragma unroll
        for (int k = 0; k < 2; k++) {
            float snd = h2 ? wr[k] : wr[k + 2];
            float got = __shfl_xor_sync(0xFFFFFFFFu, snd, 2);
            xr[k] = (h2 ? wr[k + 2] : wr[k]) + got;
        }
        const bool h1 = (l & 1);
        float res;
        {
            float snd = h1 ? xr[0] : xr[1];
            float got = __shfl_xor_sync(0xFFFFFFFFu, snd, 1);
            res = (h1 ? xr[1] : xr[0]) + got;
        }
        if (l < 8) part[t & 1][w][l] = res;   // partial for row rowbase+l, quadrant q
        __syncthreads();

        // warp 0 lanes 0..15: combine 4 quadrants, tanh, store (value,tag) pair
        if (isOut) {
            const int r  = l & 7;
            const int g2 = l >> 3;
            const float* pf = &part[t & 1][g2 * 4][0];
            float d = pf[0 * 8 + r] + pf[1 * 8 + r] + pf[2 * 8 + r] + pf[3 * 8 + r];
            // s_new = 0.5*s_prev + 0.5*tanh(u + 0.5*(W s_prev))
            float snew = 0.5f * s_my + 0.5f * tanh_acc(fmaf(0.5f, d, uval));
            s_my = snew;
            pair_st(g_sp + (size_t)(t + 1) * RDIM + outrow,
                    __float_as_uint(snew), (unsigned)(t + 1));
        }
    }
}

// =============================================================================
// Kernel 3: predictions[t][o] = sum_r states_t[r] * Wout[r][o]
// states read from the pair buffer (.x lanes of g_sp rows 1..T)
// =============================================================================
__global__ __launch_bounds__(256) void k_out(const float* __restrict__ wout,
                                             float* __restrict__ pred) {
    __shared__ float As[64][68];  // As[k][t]
    __shared__ float Bs[64][68];  // Bs[k][o]
    const int t0 = blockIdx.x * 64;
    const int tid = threadIdx.x;
    const int tx = tid & 15, ty = tid >> 4;

    float acc[4][4];
#pragma unroll
    for (int i = 0; i < 4; i++)
#pragma unroll
        for (int j = 0; j < 4; j++) acc[i][j] = 0.0f;

    for (int kc = 0; kc < RDIM; kc += 64) {
        // A tile from pair buffer: 64x64 floats = 2048 uint4 (2 pairs each)
#pragma unroll
        for (int it = 0; it < 8; it++) {
            int idx = tid + it * 256;          // 0..2047
            int tt = idx >> 5;                 // 0..63
            int k2 = idx & 31;                 // 0..31 (pairs of floats)
            uint4 v = *(const uint4*)(g_sp + (size_t)(t0 + tt + 1) * RDIM + kc + k2 * 2);
            As[k2 * 2 + 0][tt] = __uint_as_float(v.x);
            As[k2 * 2 + 1][tt] = __uint_as_float(v.z);
        }
        // B tile (wout already [k][o])
#pragma unroll
        for (int it = 0; it < 4; it++) {
            int idx = tid + it * 256;
            int kk = idx >> 4;
            int o4 = idx & 15;
            float4 vb = *(const float4*)(wout + (size_t)(kc + kk) * OUT_DIM + o4 * 4);
            *(float4*)&Bs[kk][o4 * 4] = vb;
        }
        __syncthreads();
#pragma unroll
        for (int k = 0; k < 64; k++) {
            float4 a = *(const float4*)&As[k][ty * 4];
            float4 b = *(const float4*)&Bs[k][tx * 4];
            float av[4] = {a.x, a.y, a.z, a.w};
            float bv[4] = {b.x, b.y, b.z, b.w};
#pragma unroll
            for (int i = 0; i < 4; i++)
#pragma unroll
                for (int j = 0; j < 4; j++) acc[i][j] = fmaf(av[i], bv[j], acc[i][j]);
        }
        __syncthreads();
    }
#pragma unroll
    for (int i = 0; i < 4; i++) {
        float4 o = make_float4(acc[i][0], acc[i][1], acc[i][2], acc[i][3]);
        *(float4*)(pred + (size_t)(t0 + ty * 4 + i) * OUT_DIM + tx * 4) = o;
    }
}

// =============================================================================
extern "C" void kernel_launch(void* const* d_in, const int* in_sizes, int n_in,
                              void* d_out, int out_size) {
    const float* inp  = nullptr;  // 32768*128
    const float* win  = nullptr;  // 1024*128
    const float* W    = nullptr;  // 1024*1024
    const float* wout = nullptr;  // 1024*64
    for (int i = 0; i < n_in; i++) {
        switch (in_sizes[i]) {
            case T_STEPS * IN_DIM:   inp  = (const float*)d_in[i]; break;
            case RDIM * IN_DIM:      win  = (const float*)d_in[i]; break;
            case RDIM * RDIM:        W    = (const float*)d_in[i]; break;
            case RDIM * OUT_DIM:     wout = (const float*)d_in[i]; break;
            default: break;
        }
    }
    if (!inp)  inp  = (const float*)d_in[0];
    if (!win)  win  = (const float*)d_in[1];
    if (!W)    W    = (const float*)d_in[2];
    if (!wout) wout = (const float*)d_in[3];

    k_clear<<<4096, 256>>>();
    k_u<<<dim3(T_STEPS / 64, RDIM / 64), 256>>>(inp, win);
    k_scan<<<GBLK, TPB>>>(W);
    k_out<<<T_STEPS / 64, 256>>>(wout, (float*)d_out);
}

// round 17
// speedup vs baseline: 1.1026x; 1.1026x over previous
#include <cuda_runtime.h>
#include <cstdint>

// Problem constants
#define T_STEPS   32768
#define RDIM      1024
#define IN_DIM    128
#define OUT_DIM   64

// Scan config: 64 persistent blocks x 256 threads.
// Per block: 16 rows of W. Per thread: 8 rows x 8 cols (64 fp32 weights in regs).
#define GBLK      64
#define TPB       256
#define RPB       16
#define NREP      8      // flag replicas (consumers spread over them)

// ---------------- static device scratch (no allocations allowed) -------------
__device__ float g_u[(size_t)T_STEPS * RDIM];             // 128 MB  u[t][r]
__device__ float g_states[(size_t)(T_STEPS + 1) * RDIM];  // 128 MB  row t = s_{t-1}
// Replicated flags: g_flagsR[j][r*8] = #steps completed by block j (replica r).
// Replicas 32B apart; block b polls replica (b & 7). 8 pollers per address.
__device__ int   g_flagsR[GBLK][NREP * 8];

// ---------------- init: zero flags + first state row (every launch) ---------
__global__ void k_init() {
    int tid = threadIdx.x;  // 256 threads
#pragma unroll
    for (int i = 0; i < (GBLK * NREP * 8) / 256; i++)
        ((int*)g_flagsR)[tid + i * 256] = 0;
#pragma unroll
    for (int i = 0; i < 4; i++) g_states[tid * 4 + i] = 0.0f;
}

// ---------------- accurate tanh (err ~1e-7, no overflow) --------------------
__device__ __forceinline__ float tanh_acc(float x) {
    float ax = fabsf(x);
    float z = exp2f(-2.8853900817779268f * ax);   // e^{-2|x|}
    float t = __fdividef(1.0f - z, 1.0f + z);
    return copysignf(t, x);
}

// =============================================================================
// Kernel 1: u[t][r] = sum_k input[t][k] * Win[r][k]   (NT GEMM, 64x64 tiles)
// =============================================================================
__global__ __launch_bounds__(256) void k_u(const float* __restrict__ inp,
                                           const float* __restrict__ win) {
    __shared__ float As[64][68];  // As[k][t]
    __shared__ float Bs[64][68];  // Bs[k][r]
    const int t0 = blockIdx.x * 64;
    const int r0 = blockIdx.y * 64;
    const int tid = threadIdx.x;
    const int tx = tid & 15, ty = tid >> 4;

    float acc[4][4];
#pragma unroll
    for (int i = 0; i < 4; i++)
#pragma unroll
        for (int j = 0; j < 4; j++) acc[i][j] = 0.0f;

#pragma unroll
    for (int kc = 0; kc < IN_DIM; kc += 64) {
#pragma unroll
        for (int it = 0; it < 4; it++) {
            int idx = tid + it * 256;          // 0..1023 (float4 slots)
            int tt = idx >> 4;                 // 0..63
            int k4 = idx & 15;                 // 0..15
            float4 va = *(const float4*)(inp + (size_t)(t0 + tt) * IN_DIM + kc + k4 * 4);
            As[k4 * 4 + 0][tt] = va.x; As[k4 * 4 + 1][tt] = va.y;
            As[k4 * 4 + 2][tt] = va.z; As[k4 * 4 + 3][tt] = va.w;
            float4 vb = *(const float4*)(win + (size_t)(r0 + tt) * IN_DIM + kc + k4 * 4);
            Bs[k4 * 4 + 0][tt] = vb.x; Bs[k4 * 4 + 1][tt] = vb.y;
            Bs[k4 * 4 + 2][tt] = vb.z; Bs[k4 * 4 + 3][tt] = vb.w;
        }
        __syncthreads();
#pragma unroll
        for (int k = 0; k < 64; k++) {
            float4 a = *(const float4*)&As[k][ty * 4];
            float4 b = *(const float4*)&Bs[k][tx * 4];
            float av[4] = {a.x, a.y, a.z, a.w};
            float bv[4] = {b.x, b.y, b.z, b.w};
#pragma unroll
            for (int i = 0; i < 4; i++)
#pragma unroll
                for (int j = 0; j < 4; j++) acc[i][j] = fmaf(av[i], bv[j], acc[i][j]);
        }
        __syncthreads();
    }
#pragma unroll
    for (int i = 0; i < 4; i++) {
        float4 o = make_float4(acc[i][0], acc[i][1], acc[i][2], acc[i][3]);
        *(float4*)(g_u + (size_t)(t0 + ty * 4 + i) * RDIM + r0 + tx * 4) = o;
    }
}

// =============================================================================
// Kernel 2: the scan. R9's proven acquire/release flag protocol, but flags are
// replicated 8x so each flag address has only 8 strong-pollers (not 64),
// cutting LTS strong-op same-address serialization ~8x.
// =============================================================================
__global__ __launch_bounds__(TPB, 1) void k_scan(const float* __restrict__ W) {
    const int b   = blockIdx.x;
    const int tid = threadIdx.x;
    const int w   = tid >> 5;        // warp 0..7
    const int l   = tid & 31;
    const int g   = w >> 2;          // row group 0..1 (8 rows each)
    const int q   = w & 3;           // col quadrant (256 cols)
    const int rowbase = b * RPB + g * 8;
    const int cbase   = q * 256 + l * 8;

    // 8x8 weight tile in registers for the whole scan
    float4 wv[8][2];
#pragma unroll
    for (int i = 0; i < 8; i++) {
        const float4* p = (const float4*)(W + (size_t)(rowbase + i) * RDIM + cbase);
        wv[i][0] = p[0];
        wv[i][1] = p[1];
    }

    __shared__ float part[2][8][8];  // [parity][warp][row-in-group]

    const bool isOut = (w == 0 && l < 16);
    const int outrow = b * RPB + l;  // valid when isOut
    const int rep = (b & (NREP - 1)) * 8;   // my flag replica slot
    float s_my = 0.0f;

    for (int t = 0; t < T_STEPS; t++) {
        // prefetch u[t][outrow] (latency hides under poll)
        float uval = 0.0f;
        if (isOut) uval = __ldg(&g_u[(size_t)t * RDIM + outrow]);

        // Dedicated pollers: thread j (<64) waits for block j's flag >= t,
        // reading replica (b&7). t=0 passes immediately (flags zeroed).
        if (tid < GBLK) {
            const int* fp = &g_flagsR[tid][rep];
            int f;
            do {
                asm volatile("ld.acquire.gpu.b32 %0, [%1];" : "=r"(f) : "l"(fp) : "memory");
            } while (f < t);
        }
        __syncthreads();   // acquire by pollers + cta barrier orders loads below

        // load s_{t-1}[cbase..cbase+7]  (row t of g_states; plain loads, L1 ok)
        const float4* sp = (const float4*)(g_states + (size_t)t * RDIM + cbase);
        float4 s0v = sp[0], s1v = sp[1];
        const float s0 = s0v.x, s1 = s0v.y, s2 = s0v.z, s3 = s0v.w;
        const float s4 = s1v.x, s5 = s1v.y, s6 = s1v.z, s7 = s1v.w;

        // 64 FMAs: 8 rows x 8 cols
        float v[8];
#pragma unroll
        for (int i = 0; i < 8; i++) {
            v[i] = wv[i][0].x * s0 + wv[i][0].y * s1 + wv[i][0].z * s2 + wv[i][0].w * s3
                 + wv[i][1].x * s4 + wv[i][1].y * s5 + wv[i][1].z * s6 + wv[i][1].w * s7;
        }

        // exchange-reduction: 23 shfls; lane l<8 ends with quadrant total of row rowbase+l
#pragma unroll
        for (int j = 0; j < 8; j++) v[j] += __shfl_xor_sync(0xFFFFFFFFu, v[j], 16);
#pragma unroll
        for (int j = 0; j < 8; j++) v[j] += __shfl_xor_sync(0xFFFFFFFFu, v[j], 8);
        const bool h4 = (l & 4);
        float wr[4];
#pragma unroll
        for (int k = 0; k < 4; k++) {
            float snd = h4 ? v[k] : v[k + 4];
            float got = __shfl_xor_sync(0xFFFFFFFFu, snd, 4);
            wr[k] = (h4 ? v[k + 4] : v[k]) + got;
        }
        const bool h2 = (l & 2);
        float xr[2];
#pragma unroll
        for (int k = 0; k < 2; k++) {
            float snd = h2 ? wr[k] : wr[k + 2];
            float got = __shfl_xor_sync(0xFFFFFFFFu, snd, 2);
            xr[k] = (h2 ? wr[k + 2] : wr[k]) + got;
        }
        const bool h1 = (l & 1);
        float res;
        {
            float snd = h1 ? xr[0] : xr[1];
            float got = __shfl_xor_sync(0xFFFFFFFFu, snd, 1);
            res = (h1 ? xr[1] : xr[0]) + got;
        }
        if (l < 8) part[t & 1][w][l] = res;   // partial for row rowbase+l, quadrant q
        __syncthreads();

        // warp 0 lanes 0..15: combine 4 quadrants, tanh, publish state + flags
        if (isOut) {
            const int r  = l & 7;
            const int g2 = l >> 3;
            const float* pf = &part[t & 1][g2 * 4][0];
            float d = pf[0 * 8 + r] + pf[1 * 8 + r] + pf[2 * 8 + r] + pf[3 * 8 + r];
            // s_new = 0.5*s_prev + 0.5*tanh(u + 0.5*(W s_prev))
            float snew = 0.5f * s_my + 0.5f * tanh_acc(fmaf(0.5f, d, uval));
            s_my = snew;
            g_states[(size_t)(t + 1) * RDIM + outrow] = snew;  // plain store
            __syncwarp(0x0000FFFFu);   // memory-ordering barrier among lanes 0..15
            if (l == 0) {
                int vflag = t + 1;
#pragma unroll
                for (int rr = 0; rr < NREP; rr++) {
                    // release store orders the 16 state stores (via syncwarp hb)
                    asm volatile("st.release.gpu.b32 [%0], %1;"
                                 :: "l"(&g_flagsR[b][rr * 8]), "r"(vflag) : "memory");
                }
            }
        }
    }
}

// =============================================================================
// Kernel 3: predictions[t][o] = sum_r states_t[r] * Wout[r][o]
// (states_t = g_states row t+1; Wout is [1024][64] row-major = already [k][o])
// =============================================================================
__global__ __launch_bounds__(256) void k_out(const float* __restrict__ wout,
                                             float* __restrict__ pred) {
    __shared__ float As[64][68];  // As[k][t]
    __shared__ float Bs[64][68];  // Bs[k][o]
    const int t0 = blockIdx.x * 64;
    const int tid = threadIdx.x;
    const int tx = tid & 15, ty = tid >> 4;

    float acc[4][4];
#pragma unroll
    for (int i = 0; i < 4; i++)
#pragma unroll
        for (int j = 0; j < 4; j++) acc[i][j] = 0.0f;

    for (int kc = 0; kc < RDIM; kc += 64) {
#pragma unroll
        for (int it = 0; it < 4; it++) {
            int idx = tid + it * 256;
            int tt = idx >> 4;
            int k4 = idx & 15;
            float4 va = *(const float4*)(g_states + (size_t)(t0 + tt + 1) * RDIM + kc + k4 * 4);
            As[k4 * 4 + 0][tt] = va.x; As[k4 * 4 + 1][tt] = va.y;
            As[k4 * 4 + 2][tt] = va.z; As[k4 * 4 + 3][tt] = va.w;
            int kk = idx >> 4;
            int o4 = idx & 15;
            float4 vb = *(const float4*)(wout + (size_t)(kc + kk) * OUT_DIM + o4 * 4);
            *(float4*)&Bs[kk][o4 * 4] = vb;
        }
        __syncthreads();
#pragma unroll
        for (int k = 0; k < 64; k++) {
            float4 a = *(const float4*)&As[k][ty * 4];
            float4 b = *(const float4*)&Bs[k][tx * 4];
            float av[4] = {a.x, a.y, a.z, a.w};
            float bv[4] = {b.x, b.y, b.z, b.w};
#pragma unroll
            for (int i = 0; i < 4; i++)
#pragma unroll
                for (int j = 0; j < 4; j++) acc[i][j] = fmaf(av[i], bv[j], acc[i][j]);
        }
        __syncthreads();
    }
#pragma unroll
    for (int i = 0; i < 4; i++) {
        float4 o = make_float4(acc[i][0], acc[i][1], acc[i][2], acc[i][3]);
        *(float4*)(pred + (size_t)(t0 + ty * 4 + i) * OUT_DIM + tx * 4) = o;
    }
}

// =============================================================================
extern "C" void kernel_launch(void* const* d_in, const int* in_sizes, int n_in,
                              void* d_out, int out_size) {
    const float* inp  = nullptr;  // 32768*128
    const float* win  = nullptr;  // 1024*128
    const float* W    = nullptr;  // 1024*1024
    const float* wout = nullptr;  // 1024*64
    for (int i = 0; i < n_in; i++) {
        switch (in_sizes[i]) {
            case T_STEPS * IN_DIM:   inp  = (const float*)d_in[i]; break;
            case RDIM * IN_DIM:      win  = (const float*)d_in[i]; break;
            case RDIM * RDIM:        W    = (const float*)d_in[i]; break;
            case RDIM * OUT_DIM:     wout = (const float*)d_in[i]; break;
            default: break;
        }
    }
    if (!inp)  inp  = (const float*)d_in[0];
    if (!win)  win  = (const float*)d_in[1];
    if (!W)    W    = (const float*)d_in[2];
    if (!wout) wout = (const float*)d_in[3];

    k_init<<<1, 256>>>();
    k_u<<<dim3(T_STEPS / 64, RDIM / 64), 256>>>(inp, win);
    k_scan<<<GBLK, TPB>>>(W);
    k_out<<<T_STEPS / 64, 256>>>(wout, (float*)d_out);
}